// round 11
// baseline (speedup 1.0000x reference)
#include <cuda_runtime.h>
#include <math.h>

// Problem constants
#define NN 100000
#define EE 1280000
#define FDIM 64
#define CDIM 40

// Scratch (static __device__ globals: no allocation allowed)
__device__ int   g_is64;
__device__ int   g_deg[NN];
__device__ int   g_cur[NN];
__device__ int   g_off[NN + 1];
__device__ float g_dinv[NN];
__device__ int2  g_csr[EE];                    // {src, bitcast(weight)}
__device__ float g_h0[(size_t)NN * FDIM];
__device__ float g_h1[(size_t)NN * FDIM];

// ---------------------------------------------------------------------------
// Detect whether edge_index is int64 or int32. With int64 data (values <
// 100000 << 2^31) every odd 32-bit word is a zero high-word; with genuine
// int32 random indices that is (prob ~0) never true for 256 samples.
__global__ void k_detect(const int* __restrict__ ei32) {
    int any = 0;
    for (int i = 1; i < 512; i += 2) any |= ei32[i];
    g_is64 = (any == 0) ? 1 : 0;
}

__device__ __forceinline__ int edge_at(const void* ei, size_t idx, int is64) {
    if (is64) return (int)((const long long*)ei)[idx];
    return ((const int*)ei)[idx];
}

__global__ void k_zero(int n) {
    int i = blockIdx.x * blockDim.x + threadIdx.x;
    if (i < n) { g_deg[i] = 0; g_cur[i] = 0; }
}

// in-degree of real edges (self loops handled analytically: deg = in_deg + 1)
__global__ void k_count(const void* __restrict__ ei, int E) {
    int is64 = g_is64;
    int e = blockIdx.x * blockDim.x + threadIdx.x;
    if (e < E) {
        int d = edge_at(ei, (size_t)E + e, is64);
        atomicAdd(&g_deg[d], 1);
    }
}

__global__ void k_dinv(int n) {
    int i = blockIdx.x * blockDim.x + threadIdx.x;
    if (i < n) g_dinv[i] = rsqrtf((float)g_deg[i] + 1.0f);
}

// Single-block exclusive scan of g_deg -> g_off
__global__ void k_scan(int n) {
    const int T = 1024;
    int tid = threadIdx.x;
    int per = (n + T - 1) / T;
    int s0 = tid * per;
    int s1 = min(s0 + per, n);
    int sum = 0;
    for (int i = s0; i < s1; i++) sum += g_deg[i];
    __shared__ int sh[T];
    sh[tid] = sum;
    __syncthreads();
    for (int off = 1; off < T; off <<= 1) {
        int v = 0;
        if (tid >= off) v = sh[tid - off];
        __syncthreads();
        sh[tid] += v;
        __syncthreads();
    }
    int run = (tid == 0) ? 0 : sh[tid - 1];
    for (int i = s0; i < s1; i++) { g_off[i] = run; run += g_deg[i]; }
    if (tid == T - 1) g_off[n] = run;   // = E
}

// Fill CSR: slot each edge under its dst; pack src + precomputed weight.
__global__ void k_fill(const void* __restrict__ ei, int E) {
    int is64 = g_is64;
    int e = blockIdx.x * blockDim.x + threadIdx.x;
    if (e < E) {
        int s = edge_at(ei, (size_t)e, is64);
        int d = edge_at(ei, (size_t)E + e, is64);
        int pos = g_off[d] + atomicAdd(&g_cur[d], 1);
        float w = g_dinv[s] * g_dinv[d];
        g_csr[pos] = make_int2(s, __float_as_int(w));
    }
}

// One propagation hop: h_out[v] = dinv[v]^2*h_in[v] + sum_in-edges w*h_in[src]
// Warp per node; lane owns 2 features (float2 => coalesced 256B per edge).
// mode 0: x -> g_h1 ; mode 1: g_h1 -> g_h0 ; mode 2: g_h0 -> g_h1
__global__ void k_gather(int mode, const float* __restrict__ x, int n) {
    int w = (blockIdx.x * blockDim.x + threadIdx.x) >> 5;
    int lane = threadIdx.x & 31;
    if (w >= n) return;

    const float* __restrict__ hin = (mode == 0) ? x : ((mode == 1) ? g_h1 : g_h0);
    float* __restrict__ hout = (mode == 1) ? g_h0 : g_h1;

    float di = g_dinv[w];
    float2 hv = ((const float2*)(hin + (size_t)w * FDIM))[lane];
    float ax = di * di * hv.x;
    float ay = di * di * hv.y;

    int beg = g_off[w], end = g_off[w + 1];
    int j = beg;
    for (; j + 1 < end; j += 2) {
        int2 e0 = g_csr[j];
        int2 e1 = g_csr[j + 1];
        float2 a = __ldg((const float2*)(hin + (size_t)e0.x * FDIM) + lane);
        float2 b = __ldg((const float2*)(hin + (size_t)e1.x * FDIM) + lane);
        float w0 = __int_as_float(e0.y);
        float w1 = __int_as_float(e1.y);
        ax += w0 * a.x; ay += w0 * a.y;
        ax += w1 * b.x; ay += w1 * b.y;
    }
    if (j < end) {
        int2 e0 = g_csr[j];
        float2 a = __ldg((const float2*)(hin + (size_t)e0.x * FDIM) + lane);
        float w0 = __int_as_float(e0.y);
        ax += w0 * a.x; ay += w0 * a.y;
    }
    ((float2*)(hout + (size_t)w * FDIM))[lane] = make_float2(ax, ay);
}

// Fused linear (h @ W^T + b) + log_softmax. Thread per node.
__global__ void k_out(const float* __restrict__ W,
                      const float* __restrict__ b,
                      float* __restrict__ out, int n) {
    __shared__ float4 sW[CDIM * (FDIM / 4)];
    __shared__ float sb[CDIM];
    for (int i = threadIdx.x; i < CDIM * (FDIM / 4); i += blockDim.x)
        sW[i] = ((const float4*)W)[i];
    if (threadIdx.x < CDIM) sb[threadIdx.x] = b[threadIdx.x];
    __syncthreads();

    int v = blockIdx.x * blockDim.x + threadIdx.x;
    if (v >= n) return;

    float logit[CDIM];
#pragma unroll
    for (int c = 0; c < CDIM; c++) logit[c] = sb[c];

    const float4* hr = (const float4*)(g_h1 + (size_t)v * FDIM);
#pragma unroll
    for (int q = 0; q < FDIM / 4; q++) {
        float4 hv = __ldg(hr + q);
#pragma unroll
        for (int c = 0; c < CDIM; c++) {
            float4 wv = sW[c * (FDIM / 4) + q];
            logit[c] += hv.x * wv.x + hv.y * wv.y + hv.z * wv.z + hv.w * wv.w;
        }
    }

    float m = logit[0];
#pragma unroll
    for (int c = 1; c < CDIM; c++) m = fmaxf(m, logit[c]);
    float s = 0.0f;
#pragma unroll
    for (int c = 0; c < CDIM; c++) s += expf(logit[c] - m);
    float lse = m + logf(s);

    float4* o = (float4*)(out + (size_t)v * CDIM);
#pragma unroll
    for (int q = 0; q < CDIM / 4; q++) {
        o[q] = make_float4(logit[4 * q + 0] - lse, logit[4 * q + 1] - lse,
                           logit[4 * q + 2] - lse, logit[4 * q + 3] - lse);
    }
}

// ---------------------------------------------------------------------------
extern "C" void kernel_launch(void* const* d_in, const int* in_sizes, int n_in,
                              void* d_out, int out_size) {
    const float* x   = (const float*)d_in[0];   // [N,64] f32
    const void*  ei  = d_in[1];                 // [2,E] i32 or i64
    const float* W   = (const float*)d_in[2];   // [40,64] f32
    const float* b   = (const float*)d_in[3];   // [40] f32
    float*       out = (float*)d_out;           // [N,40] f32

    int N = in_sizes[0] / FDIM;   // 100000
    int E = in_sizes[1] / 2;      // 1280000

    const int TB = 256;
    k_detect<<<1, 1>>>((const int*)ei);
    k_zero <<<(N + TB - 1) / TB, TB>>>(N);
    k_count<<<(E + TB - 1) / TB, TB>>>(ei, E);
    k_dinv <<<(N + TB - 1) / TB, TB>>>(N);
    k_scan <<<1, 1024>>>(N);
    k_fill <<<(E + TB - 1) / TB, TB>>>(ei, E);

    int gblocks = (N * 32 + TB - 1) / TB;   // warp per node
    k_gather<<<gblocks, TB>>>(0, x, N);     // x    -> g_h1
    k_gather<<<gblocks, TB>>>(1, x, N);     // g_h1 -> g_h0
    k_gather<<<gblocks, TB>>>(2, x, N);     // g_h0 -> g_h1

    k_out<<<(N + TB - 1) / TB, TB>>>(W, b, out, N);
}

// round 12
// speedup vs baseline: 1.0038x; 1.0038x over previous
#include <cuda_runtime.h>
#include <math.h>

// Problem constants
#define NN 100000
#define EE 1280000
#define FDIM 64
#define CDIM 40

// Scratch (static __device__ globals: no allocation allowed)
__device__ int   g_is64;
__device__ int   g_deg[NN];
__device__ int   g_cur[NN];
__device__ int   g_off[NN + 1];
__device__ float g_dinv[NN];
__device__ int2  g_csr[EE];                    // {src, bitcast(weight)}
__device__ float g_h0[(size_t)NN * FDIM];
__device__ float g_h1[(size_t)NN * FDIM];

// ---------------------------------------------------------------------------
// Detect whether edge_index is int64 or int32. With int64 data (values <
// 100000 << 2^31) every odd 32-bit word is a zero high-word; with genuine
// int32 random indices that is (prob ~0) never true for 256 samples.
__global__ void k_detect(const int* __restrict__ ei32) {
    int any = 0;
    for (int i = 1; i < 512; i += 2) any |= ei32[i];
    g_is64 = (any == 0) ? 1 : 0;
}

__device__ __forceinline__ int edge_at(const void* ei, size_t idx, int is64) {
    if (is64) return (int)((const long long*)ei)[idx];
    return ((const int*)ei)[idx];
}

__global__ void k_zero(int n) {
    int i = blockIdx.x * blockDim.x + threadIdx.x;
    if (i < n) { g_deg[i] = 0; g_cur[i] = 0; }
}

// in-degree of real edges (self loops handled analytically: deg = in_deg + 1)
__global__ void k_count(const void* __restrict__ ei, int E) {
    int is64 = g_is64;
    int e = blockIdx.x * blockDim.x + threadIdx.x;
    if (e < E) {
        int d = edge_at(ei, (size_t)E + e, is64);
        atomicAdd(&g_deg[d], 1);
    }
}

__global__ void k_dinv(int n) {
    int i = blockIdx.x * blockDim.x + threadIdx.x;
    if (i < n) g_dinv[i] = rsqrtf((float)g_deg[i] + 1.0f);
}

// Single-block exclusive scan of g_deg -> g_off
__global__ void k_scan(int n) {
    const int T = 1024;
    int tid = threadIdx.x;
    int per = (n + T - 1) / T;
    int s0 = tid * per;
    int s1 = min(s0 + per, n);
    int sum = 0;
    for (int i = s0; i < s1; i++) sum += g_deg[i];
    __shared__ int sh[T];
    sh[tid] = sum;
    __syncthreads();
    for (int off = 1; off < T; off <<= 1) {
        int v = 0;
        if (tid >= off) v = sh[tid - off];
        __syncthreads();
        sh[tid] += v;
        __syncthreads();
    }
    int run = (tid == 0) ? 0 : sh[tid - 1];
    for (int i = s0; i < s1; i++) { g_off[i] = run; run += g_deg[i]; }
    if (tid == T - 1) g_off[n] = run;   // = E
}

// Fill CSR: slot each edge under its dst; pack src + precomputed weight.
__global__ void k_fill(const void* __restrict__ ei, int E) {
    int is64 = g_is64;
    int e = blockIdx.x * blockDim.x + threadIdx.x;
    if (e < E) {
        int s = edge_at(ei, (size_t)e, is64);
        int d = edge_at(ei, (size_t)E + e, is64);
        int pos = g_off[d] + atomicAdd(&g_cur[d], 1);
        float w = g_dinv[s] * g_dinv[d];
        g_csr[pos] = make_int2(s, __float_as_int(w));
    }
}

// One propagation hop: h_out[v] = dinv[v]^2*h_in[v] + sum_in-edges w*h_in[src]
// Warp per node; lane owns 2 features (float2 => coalesced 256B per edge).
// mode 0: x -> g_h1 ; mode 1: g_h1 -> g_h0 ; mode 2: g_h0 -> g_h1
__global__ void k_gather(int mode, const float* __restrict__ x, int n) {
    int w = (blockIdx.x * blockDim.x + threadIdx.x) >> 5;
    int lane = threadIdx.x & 31;
    if (w >= n) return;

    const float* __restrict__ hin = (mode == 0) ? x : ((mode == 1) ? g_h1 : g_h0);
    float* __restrict__ hout = (mode == 1) ? g_h0 : g_h1;

    float di = g_dinv[w];
    float2 hv = ((const float2*)(hin + (size_t)w * FDIM))[lane];
    float ax = di * di * hv.x;
    float ay = di * di * hv.y;

    int beg = g_off[w], end = g_off[w + 1];
    int j = beg;
    for (; j + 1 < end; j += 2) {
        int2 e0 = g_csr[j];
        int2 e1 = g_csr[j + 1];
        float2 a = __ldg((const float2*)(hin + (size_t)e0.x * FDIM) + lane);
        float2 b = __ldg((const float2*)(hin + (size_t)e1.x * FDIM) + lane);
        float w0 = __int_as_float(e0.y);
        float w1 = __int_as_float(e1.y);
        ax += w0 * a.x; ay += w0 * a.y;
        ax += w1 * b.x; ay += w1 * b.y;
    }
    if (j < end) {
        int2 e0 = g_csr[j];
        float2 a = __ldg((const float2*)(hin + (size_t)e0.x * FDIM) + lane);
        float w0 = __int_as_float(e0.y);
        ax += w0 * a.x; ay += w0 * a.y;
    }
    ((float2*)(hout + (size_t)w * FDIM))[lane] = make_float2(ax, ay);
}

// Fused linear (h @ W^T + b) + log_softmax. Thread per node.
__global__ void k_out(const float* __restrict__ W,
                      const float* __restrict__ b,
                      float* __restrict__ out, int n) {
    __shared__ float4 sW[CDIM * (FDIM / 4)];
    __shared__ float sb[CDIM];
    for (int i = threadIdx.x; i < CDIM * (FDIM / 4); i += blockDim.x)
        sW[i] = ((const float4*)W)[i];
    if (threadIdx.x < CDIM) sb[threadIdx.x] = b[threadIdx.x];
    __syncthreads();

    int v = blockIdx.x * blockDim.x + threadIdx.x;
    if (v >= n) return;

    float logit[CDIM];
#pragma unroll
    for (int c = 0; c < CDIM; c++) logit[c] = sb[c];

    const float4* hr = (const float4*)(g_h1 + (size_t)v * FDIM);
#pragma unroll
    for (int q = 0; q < FDIM / 4; q++) {
        float4 hv = __ldg(hr + q);
#pragma unroll
        for (int c = 0; c < CDIM; c++) {
            float4 wv = sW[c * (FDIM / 4) + q];
            logit[c] += hv.x * wv.x + hv.y * wv.y + hv.z * wv.z + hv.w * wv.w;
        }
    }

    float m = logit[0];
#pragma unroll
    for (int c = 1; c < CDIM; c++) m = fmaxf(m, logit[c]);
    float s = 0.0f;
#pragma unroll
    for (int c = 0; c < CDIM; c++) s += expf(logit[c] - m);
    float lse = m + logf(s);

    float4* o = (float4*)(out + (size_t)v * CDIM);
#pragma unroll
    for (int q = 0; q < CDIM / 4; q++) {
        o[q] = make_float4(logit[4 * q + 0] - lse, logit[4 * q + 1] - lse,
                           logit[4 * q + 2] - lse, logit[4 * q + 3] - lse);
    }
}

// ---------------------------------------------------------------------------
extern "C" void kernel_launch(void* const* d_in, const int* in_sizes, int n_in,
                              void* d_out, int out_size) {
    const float* x   = (const float*)d_in[0];   // [N,64] f32
    const void*  ei  = d_in[1];                 // [2,E] i32 or i64
    const float* W   = (const float*)d_in[2];   // [40,64] f32
    const float* b   = (const float*)d_in[3];   // [40] f32
    float*       out = (float*)d_out;           // [N,40] f32

    int N = in_sizes[0] / FDIM;   // 100000
    int E = in_sizes[1] / 2;      // 1280000

    const int TB = 256;
    k_detect<<<1, 1>>>((const int*)ei);
    k_zero <<<(N + TB - 1) / TB, TB>>>(N);
    k_count<<<(E + TB - 1) / TB, TB>>>(ei, E);
    k_dinv <<<(N + TB - 1) / TB, TB>>>(N);
    k_scan <<<1, 1024>>>(N);
    k_fill <<<(E + TB - 1) / TB, TB>>>(ei, E);

    int gblocks = (N * 32 + TB - 1) / TB;   // warp per node
    k_gather<<<gblocks, TB>>>(0, x, N);     // x    -> g_h1
    k_gather<<<gblocks, TB>>>(1, x, N);     // g_h1 -> g_h0
    k_gather<<<gblocks, TB>>>(2, x, N);     // g_h0 -> g_h1

    k_out<<<(N + TB - 1) / TB, TB>>>(W, b, out, N);
}

// round 13
// speedup vs baseline: 1.0073x; 1.0035x over previous
#include <cuda_runtime.h>
#include <math.h>

// Problem constants
#define NN 100000
#define EE 1280000
#define FDIM 64
#define CDIM 40

// Scratch (static __device__ globals: no allocation allowed)
__device__ int   g_is64;
__device__ int   g_deg[NN];
__device__ int   g_cur[NN];
__device__ int   g_off[NN + 1];
__device__ float g_dinv[NN];
__device__ int2  g_csr[EE];                    // {src, bitcast(weight)}
__device__ float g_h0[(size_t)NN * FDIM];
__device__ float g_h1[(size_t)NN * FDIM];

// ---------------------------------------------------------------------------
// Detect whether edge_index is int64 or int32. With int64 data (values <
// 100000 << 2^31) every odd 32-bit word is a zero high-word; with genuine
// int32 random indices that is (prob ~0) never true for 256 samples.
__global__ void k_detect(const int* __restrict__ ei32) {
    int any = 0;
    for (int i = 1; i < 512; i += 2) any |= ei32[i];
    g_is64 = (any == 0) ? 1 : 0;
}

__device__ __forceinline__ int edge_at(const void* ei, size_t idx, int is64) {
    if (is64) return (int)((const long long*)ei)[idx];
    return ((const int*)ei)[idx];
}

__global__ void k_zero(int n) {
    int i = blockIdx.x * blockDim.x + threadIdx.x;
    if (i < n) { g_deg[i] = 0; g_cur[i] = 0; }
}

// in-degree of real edges (self loops handled analytically: deg = in_deg + 1)
__global__ void k_count(const void* __restrict__ ei, int E) {
    int is64 = g_is64;
    int e = blockIdx.x * blockDim.x + threadIdx.x;
    if (e < E) {
        int d = edge_at(ei, (size_t)E + e, is64);
        atomicAdd(&g_deg[d], 1);
    }
}

__global__ void k_dinv(int n) {
    int i = blockIdx.x * blockDim.x + threadIdx.x;
    if (i < n) g_dinv[i] = rsqrtf((float)g_deg[i] + 1.0f);
}

// Single-block exclusive scan of g_deg -> g_off
__global__ void k_scan(int n) {
    const int T = 1024;
    int tid = threadIdx.x;
    int per = (n + T - 1) / T;
    int s0 = tid * per;
    int s1 = min(s0 + per, n);
    int sum = 0;
    for (int i = s0; i < s1; i++) sum += g_deg[i];
    __shared__ int sh[T];
    sh[tid] = sum;
    __syncthreads();
    for (int off = 1; off < T; off <<= 1) {
        int v = 0;
        if (tid >= off) v = sh[tid - off];
        __syncthreads();
        sh[tid] += v;
        __syncthreads();
    }
    int run = (tid == 0) ? 0 : sh[tid - 1];
    for (int i = s0; i < s1; i++) { g_off[i] = run; run += g_deg[i]; }
    if (tid == T - 1) g_off[n] = run;   // = E
}

// Fill CSR: slot each edge under its dst; pack src + precomputed weight.
__global__ void k_fill(const void* __restrict__ ei, int E) {
    int is64 = g_is64;
    int e = blockIdx.x * blockDim.x + threadIdx.x;
    if (e < E) {
        int s = edge_at(ei, (size_t)e, is64);
        int d = edge_at(ei, (size_t)E + e, is64);
        int pos = g_off[d] + atomicAdd(&g_cur[d], 1);
        float w = g_dinv[s] * g_dinv[d];
        g_csr[pos] = make_int2(s, __float_as_int(w));
    }
}

// One propagation hop: h_out[v] = dinv[v]^2*h_in[v] + sum_in-edges w*h_in[src]
// Warp per node; lane owns 2 features (float2 => coalesced 256B per edge).
// mode 0: x -> g_h1 ; mode 1: g_h1 -> g_h0 ; mode 2: g_h0 -> g_h1
__global__ void k_gather(int mode, const float* __restrict__ x, int n) {
    int w = (blockIdx.x * blockDim.x + threadIdx.x) >> 5;
    int lane = threadIdx.x & 31;
    if (w >= n) return;

    const float* __restrict__ hin = (mode == 0) ? x : ((mode == 1) ? g_h1 : g_h0);
    float* __restrict__ hout = (mode == 1) ? g_h0 : g_h1;

    float di = g_dinv[w];
    float2 hv = ((const float2*)(hin + (size_t)w * FDIM))[lane];
    float ax = di * di * hv.x;
    float ay = di * di * hv.y;

    int beg = g_off[w], end = g_off[w + 1];
    int j = beg;
    for (; j + 1 < end; j += 2) {
        int2 e0 = g_csr[j];
        int2 e1 = g_csr[j + 1];
        float2 a = __ldg((const float2*)(hin + (size_t)e0.x * FDIM) + lane);
        float2 b = __ldg((const float2*)(hin + (size_t)e1.x * FDIM) + lane);
        float w0 = __int_as_float(e0.y);
        float w1 = __int_as_float(e1.y);
        ax += w0 * a.x; ay += w0 * a.y;
        ax += w1 * b.x; ay += w1 * b.y;
    }
    if (j < end) {
        int2 e0 = g_csr[j];
        float2 a = __ldg((const float2*)(hin + (size_t)e0.x * FDIM) + lane);
        float w0 = __int_as_float(e0.y);
        ax += w0 * a.x; ay += w0 * a.y;
    }
    ((float2*)(hout + (size_t)w * FDIM))[lane] = make_float2(ax, ay);
}

// Fused linear (h @ W^T + b) + log_softmax. Thread per node.
__global__ void k_out(const float* __restrict__ W,
                      const float* __restrict__ b,
                      float* __restrict__ out, int n) {
    __shared__ float4 sW[CDIM * (FDIM / 4)];
    __shared__ float sb[CDIM];
    for (int i = threadIdx.x; i < CDIM * (FDIM / 4); i += blockDim.x)
        sW[i] = ((const float4*)W)[i];
    if (threadIdx.x < CDIM) sb[threadIdx.x] = b[threadIdx.x];
    __syncthreads();

    int v = blockIdx.x * blockDim.x + threadIdx.x;
    if (v >= n) return;

    float logit[CDIM];
#pragma unroll
    for (int c = 0; c < CDIM; c++) logit[c] = sb[c];

    const float4* hr = (const float4*)(g_h1 + (size_t)v * FDIM);
#pragma unroll
    for (int q = 0; q < FDIM / 4; q++) {
        float4 hv = __ldg(hr + q);
#pragma unroll
        for (int c = 0; c < CDIM; c++) {
            float4 wv = sW[c * (FDIM / 4) + q];
            logit[c] += hv.x * wv.x + hv.y * wv.y + hv.z * wv.z + hv.w * wv.w;
        }
    }

    float m = logit[0];
#pragma unroll
    for (int c = 1; c < CDIM; c++) m = fmaxf(m, logit[c]);
    float s = 0.0f;
#pragma unroll
    for (int c = 0; c < CDIM; c++) s += expf(logit[c] - m);
    float lse = m + logf(s);

    float4* o = (float4*)(out + (size_t)v * CDIM);
#pragma unroll
    for (int q = 0; q < CDIM / 4; q++) {
        o[q] = make_float4(logit[4 * q + 0] - lse, logit[4 * q + 1] - lse,
                           logit[4 * q + 2] - lse, logit[4 * q + 3] - lse);
    }
}

// ---------------------------------------------------------------------------
extern "C" void kernel_launch(void* const* d_in, const int* in_sizes, int n_in,
                              void* d_out, int out_size) {
    const float* x   = (const float*)d_in[0];   // [N,64] f32
    const void*  ei  = d_in[1];                 // [2,E] i32 or i64
    const float* W   = (const float*)d_in[2];   // [40,64] f32
    const float* b   = (const float*)d_in[3];   // [40] f32
    float*       out = (float*)d_out;           // [N,40] f32

    int N = in_sizes[0] / FDIM;   // 100000
    int E = in_sizes[1] / 2;      // 1280000

    const int TB = 256;
    k_detect<<<1, 1>>>((const int*)ei);
    k_zero <<<(N + TB - 1) / TB, TB>>>(N);
    k_count<<<(E + TB - 1) / TB, TB>>>(ei, E);
    k_dinv <<<(N + TB - 1) / TB, TB>>>(N);
    k_scan <<<1, 1024>>>(N);
    k_fill <<<(E + TB - 1) / TB, TB>>>(ei, E);

    int gblocks = (N * 32 + TB - 1) / TB;   // warp per node
    k_gather<<<gblocks, TB>>>(0, x, N);     // x    -> g_h1
    k_gather<<<gblocks, TB>>>(1, x, N);     // g_h1 -> g_h0
    k_gather<<<gblocks, TB>>>(2, x, N);     // g_h0 -> g_h1

    k_out<<<(N + TB - 1) / TB, TB>>>(W, b, out, N);
}